// round 15
// baseline (speedup 1.0000x reference)
#include <cuda_runtime.h>
#include <math.h>
#include <stdint.h>

#define NSLICE 1088          // 64 * 17 slices per tensor
#define HW     16384         // 128 * 128
#define MAX_DIST 181.02f
#define NCTA 296             // 2 CTAs/SM
#define NTH  512             // 16 warps; at most 8 busy (one slice per warp)

__device__ float g_acc = 0.0f;       // global loss accumulator (reset by last CTA)
__device__ unsigned int g_done = 0u; // CTA completion counter (reset by last CTA)

__device__ __forceinline__ float fsqrt_approx(float x) {
    float r;
    asm("sqrt.approx.f32 %0, %1;" : "=f"(r) : "f"(x));
    return r;
}
__device__ __forceinline__ float max4(float4 q) {
    return fmaxf(fmaxf(q.x, q.y), fmaxf(q.z, q.w));
}

// ---------------------------------------------------------------------------
// Warp-autonomous kernel: one 128x128 slice per WARP, streamed twice with
// __ldg (pass 2 hits L2). No ring, no TMA, no mbarriers, and no block
// barriers in the slice path — each warp computes max, exact lowest-index
// argmax, and the masked mean distance entirely with warp shuffles.
// Pair layout: warps 2j / 2j+1 of a CTA handle tensors a / b of pair
// (cta + 296*j), so |d_a - d_b| is combined CTA-locally after ONE
// __syncthreads. One atomicAdd per CTA; last CTA writes the loss + resets.
// ---------------------------------------------------------------------------
__global__ void __launch_bounds__(NTH, 2) loss_kernel(const float* __restrict__ a,
                                                      const float* __restrict__ b,
                                                      float* __restrict__ out) {
    __shared__ float s_d[4][2];                // d values for up to 4 local pairs

    const int t = threadIdx.x;
    const int warp = t >> 5, lane = t & 31;
    const int cta = blockIdx.x;
    const int npair = (cta < NSLICE - 3 * NCTA) ? 4 : 3;   // cta<200: 4, else 3
    const int nslice = 2 * npair;

    if (warp < nslice) {
        const int pl = warp >> 1;              // local pair index
        const int tensor = warp & 1;           // 0 -> a, 1 -> b
        const float* base = (tensor ? b : a) + (size_t)(cta + NCTA * pl) * HW;
        const float4* p4 = (const float4*)base;

        // ---------- pass 1: max + float4-index argmax, 4 indep streams ------
        // float4 index q = lane + 32*i  ->  y = i, x = 4*lane + c
        float m0 = -1e30f, m1 = -1e30f, m2 = -1e30f, m3 = -1e30f;
        int   q0 = 0, q1 = 0, q2 = 0, q3 = 0;
        #pragma unroll 2
        for (int i = 0; i < 128; i += 4) {
            const int qa = lane + (i    ) * 32;
            const int qb = lane + (i + 1) * 32;
            const int qc = lane + (i + 2) * 32;
            const int qd = lane + (i + 3) * 32;
            float ca = max4(__ldg(p4 + qa));
            float cb = max4(__ldg(p4 + qb));
            float cc = max4(__ldg(p4 + qc));
            float cd = max4(__ldg(p4 + qd));
            if (ca > m0) { m0 = ca; q0 = qa; }  // strict >: first (lowest q) kept
            if (cb > m1) { m1 = cb; q1 = qb; }
            if (cc > m2) { m2 = cc; q2 = qc; }
            if (cd > m3) { m3 = cd; q3 = qd; }
        }
        // merge the 4 streams, lowest q wins ties (q order == e order here)
        float m = m0; int q = q0;
        if (m1 > m || (m1 == m && q1 < q)) { m = m1; q = q1; }
        if (m2 > m || (m2 == m && q2 < q)) { m = m2; q = q2; }
        if (m3 > m || (m3 == m && q3 < q)) { m = m3; q = q3; }
        // butterfly: all lanes converge on (max, lowest q). Lanes own disjoint
        // q sets, and lower q implies lower flat index e = 4q + c (c < 4).
        #pragma unroll
        for (int off = 16; off > 0; off >>= 1) {
            float om = __shfl_xor_sync(0xffffffffu, m, off);
            int   oq = __shfl_xor_sync(0xffffffffu, q, off);
            if (om > m || (om == m && oq < q)) { m = om; q = oq; }
        }
        // resolve component c by one broadcast reload of the winning float4
        const float4 vw = __ldg(p4 + q);
        const int c = (vw.x == m) ? 0 : (vw.y == m) ? 1 : (vw.z == m) ? 2 : 3;
        const int bi = (q << 2) + c;
        const float bv = m;

        // ---------- pass 2: masked distance sum (re-stream, L2 hits) --------
        const float thr = bv * 0.5f;
        const int ym = bi >> 7;
        const int xm = bi & 127;
        const int xb = (lane << 2) - xm;       // x = 4*lane + c, slice-invariant
        const float fdx2_0 = (float)(xb * xb);
        const float fdx2_1 = (float)((xb + 1) * (xb + 1));
        const float fdx2_2 = (float)((xb + 2) * (xb + 2));
        const float fdx2_3 = (float)((xb + 3) * (xb + 3));

        float sum = 0.0f;
        int   cnt = 0;
        #pragma unroll 4
        for (int i = 0; i < 128; ++i) {
            const float4 v = __ldg(p4 + lane + 32 * i);
            const int dy = i - ym;
            const float fdy2 = (float)(dy * dy);
            float d0 = fsqrt_approx(fdy2 + fdx2_0);
            float d1 = fsqrt_approx(fdy2 + fdx2_1);
            float d2 = fsqrt_approx(fdy2 + fdx2_2);
            float d3 = fsqrt_approx(fdy2 + fdx2_3);
            if (v.x > thr) { sum += d0; ++cnt; }
            if (v.y > thr) { sum += d1; ++cnt; }
            if (v.z > thr) { sum += d2; ++cnt; }
            if (v.w > thr) { sum += d3; ++cnt; }
        }
        #pragma unroll
        for (int off = 16; off > 0; off >>= 1) {
            sum += __shfl_down_sync(0xffffffffu, sum, off);
            cnt += __shfl_down_sync(0xffffffffu, cnt, off);
        }
        if (lane == 0) {
            float d;
            if (bv > 0.0f) {
                d = (cnt > 0) ? (sum / (float)cnt) / MAX_DIST : 1.0f;
            } else {
                d = 0.0f;
            }
            s_d[pl][tensor] = d;
        }
    }

    __syncthreads();                           // the ONLY block barrier

    // ---------- finalize: one atomic per CTA; last CTA writes + resets -----
    if (t == 0) {
        float acc = 0.0f;
        #pragma unroll
        for (int j = 0; j < 4; ++j)
            if (j < npair) acc += fabsf(s_d[j][0] - s_d[j][1]);
        atomicAdd(&g_acc, acc);
        __threadfence();
        unsigned int vdone = atomicAdd(&g_done, 1u);
        if (vdone == NCTA - 1) {
            float total = atomicAdd(&g_acc, 0.0f);   // serialized read after all adds
            out[0] = total / 17.0f / 64.0f;
            g_acc = 0.0f;                            // restore invariant for next run
            __threadfence();
            g_done = 0u;
        }
    }
}

extern "C" void kernel_launch(void* const* d_in, const int* in_sizes, int n_in,
                              void* d_out, int out_size) {
    const float* a = (const float*)d_in[0];   // output heatmaps [64,17,128,128] f32
    const float* b = (const float*)d_in[1];   // target heatmaps [64,17,128,128] f32
    (void)in_sizes; (void)n_in; (void)out_size;

    loss_kernel<<<NCTA, NTH>>>(a, b, (float*)d_out);
}

// round 16
// speedup vs baseline: 1.5249x; 1.5249x over previous
#include <cuda_runtime.h>
#include <math.h>
#include <stdint.h>

#define NSLICE 1088          // 64 * 17 slices per tensor
#define HW     16384         // 128 * 128
#define MAX_DIST 181.02f
#define NCTA 296             // 2 CTAs/SM
#define NTH  512
#define CHUNK_FLOATS 8192    // 32 KB chunks, 2 per slice (rows 0-63 / 64-127)
#define CHUNK_BYTES  32768
#define NRING 3              // 96 KB ring per CTA (192 KB/SM with 2 CTAs)

__device__ float g_acc = 0.0f;       // global loss accumulator (reset by last CTA)
__device__ unsigned int g_done = 0u; // CTA completion counter (reset by last CTA)

// ---------------------------------------------------------------------------
// mbarrier / bulk-copy / math helpers
// ---------------------------------------------------------------------------
__device__ __forceinline__ uint32_t smem_u32(const void* p) {
    return (uint32_t)__cvta_generic_to_shared(p);
}
__device__ __forceinline__ void mbar_init(uint32_t a, uint32_t cnt) {
    asm volatile("mbarrier.init.shared::cta.b64 [%0], %1;" :: "r"(a), "r"(cnt) : "memory");
}
__device__ __forceinline__ void mbar_arrive_expect(uint32_t a, uint32_t bytes) {
    asm volatile("mbarrier.arrive.expect_tx.shared::cta.b64 _, [%0], %1;"
                 :: "r"(a), "r"(bytes) : "memory");
}
__device__ __forceinline__ void bulk_g2s(uint32_t dst, const void* src,
                                         uint32_t bytes, uint32_t mbar) {
    asm volatile("cp.async.bulk.shared::cta.global.mbarrier::complete_tx::bytes "
                 "[%0], [%1], %2, [%3];"
                 :: "r"(dst), "l"(src), "r"(bytes), "r"(mbar) : "memory");
}
__device__ __forceinline__ void mbar_wait(uint32_t a, uint32_t parity) {
    asm volatile(
        "{\n\t.reg .pred P;\n\t"
        "WAIT_%=:\n\t"
        "mbarrier.try_wait.parity.shared::cta.b64 P, [%0], %1;\n\t"
        "@!P bra WAIT_%=;\n\t}"
        :: "r"(a), "r"(parity) : "memory");
}
__device__ __forceinline__ float fsqrt_approx(float x) {
    float r;
    asm("sqrt.approx.f32 %0, %1;" : "=f"(r) : "f"(x));
    return r;
}
__device__ __forceinline__ float max4(float4 q) {
    return fmaxf(fmaxf(q.x, q.y), fmaxf(q.z, q.w));
}

// ---------------------------------------------------------------------------
// Fused persistent kernel: 2 CTAs/SM x 512 threads, TMA ring transport,
// payload in registers, TWO barriers per slice. Pass 1 tracks the exact
// (max, lowest flat index) pair end-to-end: per-thread strict-> loop +
// select-chain component resolve, lexicographic warp butterfly, publish to
// smem, ONE barrier, lexicographic 16-entry butterfly -> every lane holds
// (bv, bi). Pass 2 masked mean distance (MUFU sqrt). One atomicAdd per CTA;
// last CTA writes the loss and resets the globals.
// ---------------------------------------------------------------------------
__global__ void __launch_bounds__(NTH, 2) loss_kernel(const float* __restrict__ a,
                                                      const float* __restrict__ b,
                                                      float* __restrict__ out) {
    extern __shared__ float ring[];            // NRING * 8192 floats (96 KB)

    __shared__ __align__(8) unsigned long long mbar_store[NRING];
    __shared__ float s_v[16];
    __shared__ int   s_e[16];
    __shared__ float s_s[16];
    __shared__ int   s_c[16];

    const int t = threadIdx.x;
    const int warp = t >> 5, lane = t & 31;    // warps 0..15
    const int cta = blockIdx.x;
    const int npair  = (NSLICE - cta + NCTA - 1) / NCTA;   // 3 or 4
    const int nslice = 2 * npair;
    const int nchunk = 2 * nslice;                          // 12 or 16

    const uint32_t mb0 = smem_u32(&mbar_store[0]);
    if (t == 0) {
        #pragma unroll
        for (int r = 0; r < NRING; ++r) mbar_init(mb0 + 8u * r, 1);
    }
    __syncthreads();

    // chunk k: pair (k>>2), tensor ((k>>1)&1), half (k&1)
    auto chunk_src = [&](int k) -> const float* {
        int p = k >> 2, which = (k >> 1) & 1, half = k & 1;
        const float* base = which ? b : a;
        return base + (size_t)(cta + p * NCTA) * HW + (size_t)half * CHUNK_FLOATS;
    };

    if (t == 0) {                              // prefill all ring slots
        #pragma unroll
        for (int k = 0; k < NRING; ++k) {
            mbar_arrive_expect(mb0 + 8u * k, CHUNK_BYTES);
            bulk_g2s(smem_u32(ring + k * CHUNK_FLOATS), chunk_src(k),
                     CHUNK_BYTES, mb0 + 8u * k);
        }
    }

    float acc = 0.0f;       // meaningful in t==0 only
    float prev_d = 0.0f;

    for (int m = 0; m < nslice; ++m) {
        const int k0 = 2 * m, k1 = 2 * m + 1;
        const int slot0 = k0 % NRING, slot1 = k1 % NRING;

        // ---------- pass 1: load 32 elems to regs, exact (max, lowest-e) ----
        float4 v[8];
        mbar_wait(mb0 + 8u * slot0, (k0 / NRING) & 1);
        {
            const float4* p = (const float4*)(ring + slot0 * CHUNK_FLOATS);
            v[0] = p[t];            v[1] = p[NTH + t];
            v[2] = p[2 * NTH + t];  v[3] = p[3 * NTH + t];
        }
        mbar_wait(mb0 + 8u * slot1, (k1 / NRING) & 1);
        {
            const float4* p = (const float4*)(ring + slot1 * CHUNK_FLOATS);
            v[4] = p[t];            v[5] = p[NTH + t];
            v[6] = p[2 * NTH + t];  v[7] = p[3 * NTH + t];
        }
        // per-thread max with lowest-j (strict > keeps the first/lowest j;
        // e is ascending in j for a fixed thread)
        float mv = max4(v[0]);
        int   jw = 0;
        #pragma unroll
        for (int j = 1; j < 8; ++j) {
            const float mx = max4(v[j]);
            if (mx > mv) { mv = mx; jw = j; }
        }
        // resolve the winning float4 without dynamic indexing (no local mem)
        float4 wv = v[0];
        #pragma unroll
        for (int j = 1; j < 8; ++j) if (jw == j) wv = v[j];
        // lowest component with the max value
        const int c = (wv.x == mv) ? 0 : (wv.y == mv) ? 1 : (wv.z == mv) ? 2 : 3;
        // e(j, c) = (j&3)*2048 + (j>>2)*8192 + 4*t + c
        int ev = ((jw & 3) << 11) + ((jw >> 2) << 13) + (t << 2) + c;

        // warp-level lexicographic (max, lowest-e) butterfly
        #pragma unroll
        for (int off = 16; off > 0; off >>= 1) {
            const float om = __shfl_xor_sync(0xffffffffu, mv, off);
            const int   oe = __shfl_xor_sync(0xffffffffu, ev, off);
            if (om > mv || (om == mv && oe < ev)) { mv = om; ev = oe; }
        }
        if (lane == 0) { s_v[warp] = mv; s_e[warp] = ev; }
        __syncthreads();                       // BAR1: ring slots now free

        // refill freed slots ASAP (warp 1; overlaps the merge below)
        if (t == 32) {
            if (k0 + NRING < nchunk) {
                mbar_arrive_expect(mb0 + 8u * slot0, CHUNK_BYTES);
                bulk_g2s(smem_u32(ring + slot0 * CHUNK_FLOATS),
                         chunk_src(k0 + NRING), CHUNK_BYTES, mb0 + 8u * slot0);
            }
            if (k1 + NRING < nchunk) {
                mbar_arrive_expect(mb0 + 8u * slot1, CHUNK_BYTES);
                bulk_g2s(smem_u32(ring + slot1 * CHUNK_FLOATS),
                         chunk_src(k1 + NRING), CHUNK_BYTES, mb0 + 8u * slot1);
            }
        }

        // block-level lexicographic merge over the 16 warp results,
        // computed redundantly by every warp (no extra barrier)
        float bv = s_v[lane & 15];
        int   bi = s_e[lane & 15];
        #pragma unroll
        for (int off = 8; off > 0; off >>= 1) {
            const float om = __shfl_xor_sync(0xffffffffu, bv, off);
            const int   oe = __shfl_xor_sync(0xffffffffu, bi, off);
            if (om > bv || (om == bv && oe < bi)) { bv = om; bi = oe; }
        }

        // ---------- pass 2: masked distance sum from registers ---------------
        const float thr = bv * 0.5f;
        const int ym = bi >> 7;
        const int xm = bi & 127;

        // x = 4*lane + c is slice-invariant per thread
        const int xb = (lane << 2) - xm;
        const float fdx2_0 = (float)(xb * xb);
        const float fdx2_1 = (float)((xb + 1) * (xb + 1));
        const float fdx2_2 = (float)((xb + 2) * (xb + 2));
        const float fdx2_3 = (float)((xb + 3) * (xb + 3));

        float sum = 0.0f;
        int   cnt = 0;
        // y(v[j]) = 16*j + warp  (j 0..7 spans both chunks contiguously in y)
        #pragma unroll
        for (int j = 0; j < 8; ++j) {
            const int dy = (j << 4) + warp - ym;
            const float fdy2 = (float)(dy * dy);
            float d0 = fsqrt_approx(fdy2 + fdx2_0);
            float d1 = fsqrt_approx(fdy2 + fdx2_1);
            float d2 = fsqrt_approx(fdy2 + fdx2_2);
            float d3 = fsqrt_approx(fdy2 + fdx2_3);
            if (v[j].x > thr) { sum += d0; ++cnt; }
            if (v[j].y > thr) { sum += d1; ++cnt; }
            if (v[j].z > thr) { sum += d2; ++cnt; }
            if (v[j].w > thr) { sum += d3; ++cnt; }
        }
        #pragma unroll
        for (int off = 16; off > 0; off >>= 1) {
            sum += __shfl_down_sync(0xffffffffu, sum, off);
            cnt += __shfl_down_sync(0xffffffffu, cnt, off);
        }
        if (lane == 0) { s_s[warp] = sum; s_c[warp] = cnt; }
        __syncthreads();                       // BAR2: all partials written

        // warp 0 reduces in parallel; shadowed by other warps entering pass 1.
        // (warp 0's reads of s_s/s_c finish before it arrives at the next
        // BAR1/BAR2, which gate the next writes to these arrays.)
        if (warp == 0) {
            float S = s_s[lane & 15];
            float C = (float)s_c[lane & 15];
            #pragma unroll
            for (int off = 8; off > 0; off >>= 1) {
                S += __shfl_xor_sync(0xffffffffu, S, off);
                C += __shfl_xor_sync(0xffffffffu, C, off);
            }
            if (lane == 0) {
                float d;
                if (bv > 0.0f) {
                    d = (C > 0.0f) ? (S / C) / MAX_DIST : 1.0f;
                } else {
                    d = 0.0f;
                }
                if (m & 1) acc += fabsf(prev_d - d);   // pair done: |d_a - d_b|
                else       prev_d = d;
            }
        }
    }

    // ---------- fused finalize: one atomic per CTA; last CTA writes + resets
    if (t == 0) {
        atomicAdd(&g_acc, acc);
        __threadfence();
        unsigned int vdone = atomicAdd(&g_done, 1u);
        if (vdone == NCTA - 1) {
            float total = atomicAdd(&g_acc, 0.0f);   // serialized read after all adds
            out[0] = total / 17.0f / 64.0f;
            g_acc = 0.0f;                            // restore invariant for next run
            __threadfence();
            g_done = 0u;
        }
    }
}

extern "C" void kernel_launch(void* const* d_in, const int* in_sizes, int n_in,
                              void* d_out, int out_size) {
    const float* a = (const float*)d_in[0];   // output heatmaps [64,17,128,128] f32
    const float* b = (const float*)d_in[1];   // target heatmaps [64,17,128,128] f32
    (void)in_sizes; (void)n_in; (void)out_size;

    const int smem_bytes = NRING * CHUNK_BYTES;   // 96 KB per CTA

    static bool attr_set = false;
    if (!attr_set) {
        cudaFuncSetAttribute(loss_kernel,
                             cudaFuncAttributeMaxDynamicSharedMemorySize, smem_bytes);
        attr_set = true;
    }

    loss_kernel<<<NCTA, NTH, smem_bytes>>>(a, b, (float*)d_out);
}

// round 17
// speedup vs baseline: 1.6298x; 1.0688x over previous
#include <cuda_runtime.h>
#include <math.h>
#include <stdint.h>

#define NSLICE 1088          // 64 * 17 slices per tensor
#define HW     16384         // 128 * 128
#define MAX_DIST 181.02f
#define NCTA 296             // 2 CTAs/SM
#define NTH  512
#define CHUNK_FLOATS 8192    // 32 KB chunks, 2 per slice (rows 0-63 / 64-127)
#define CHUNK_BYTES  32768
#define NRING 3              // 96 KB ring per CTA (192 KB/SM with 2 CTAs)

__device__ float g_acc = 0.0f;       // global loss accumulator (reset by last CTA)
__device__ unsigned int g_done = 0u; // CTA completion counter (reset by last CTA)

// ---------------------------------------------------------------------------
// mbarrier / bulk-copy / math helpers
// ---------------------------------------------------------------------------
__device__ __forceinline__ uint32_t smem_u32(const void* p) {
    return (uint32_t)__cvta_generic_to_shared(p);
}
__device__ __forceinline__ void mbar_init(uint32_t a, uint32_t cnt) {
    asm volatile("mbarrier.init.shared::cta.b64 [%0], %1;" :: "r"(a), "r"(cnt) : "memory");
}
__device__ __forceinline__ void mbar_arrive_expect(uint32_t a, uint32_t bytes) {
    asm volatile("mbarrier.arrive.expect_tx.shared::cta.b64 _, [%0], %1;"
                 :: "r"(a), "r"(bytes) : "memory");
}
__device__ __forceinline__ void bulk_g2s(uint32_t dst, const void* src,
                                         uint32_t bytes, uint32_t mbar) {
    asm volatile("cp.async.bulk.shared::cta.global.mbarrier::complete_tx::bytes "
                 "[%0], [%1], %2, [%3];"
                 :: "r"(dst), "l"(src), "r"(bytes), "r"(mbar) : "memory");
}
__device__ __forceinline__ void mbar_wait(uint32_t a, uint32_t parity) {
    asm volatile(
        "{\n\t.reg .pred P;\n\t"
        "WAIT_%=:\n\t"
        "mbarrier.try_wait.parity.shared::cta.b64 P, [%0], %1;\n\t"
        "@!P bra WAIT_%=;\n\t}"
        :: "r"(a), "r"(parity) : "memory");
}
__device__ __forceinline__ float fsqrt_approx(float x) {
    float r;
    asm("sqrt.approx.f32 %0, %1;" : "=f"(r) : "f"(x));
    return r;
}
__device__ __forceinline__ float max4(float4 q) {
    return fmaxf(fmaxf(q.x, q.y), fmaxf(q.z, q.w));
}

// ---------------------------------------------------------------------------
// Fused persistent kernel: 2 CTAs/SM x 512 threads, TMA ring transport,
// payload in registers, TWO barriers per slice with near-zero reduction ALU:
// warp (max, lowest-e) via two redux.sync ops; block merge via ONE packed
// 64-bit shared atomicMax per warp ((value_bits<<32)|(16384-e): higher value
// wins, ties pick lower e). After BAR1 every thread reads (bv, bi) with one
// LDS.64 — no rescan, no second butterfly. Pass 2 masked mean distance (MUFU
// sqrt). One atomicAdd per CTA; last CTA writes the loss and resets globals.
// ---------------------------------------------------------------------------
__global__ void __launch_bounds__(NTH, 2) loss_kernel(const float* __restrict__ a,
                                                      const float* __restrict__ b,
                                                      float* __restrict__ out) {
    extern __shared__ float ring[];            // NRING * 8192 floats (96 KB)

    __shared__ __align__(8) unsigned long long mbar_store[NRING];
    __shared__ unsigned long long s_pack[2];   // ping-pong (value, 16384-e)
    __shared__ float s_s[16];
    __shared__ int   s_c[16];

    const int t = threadIdx.x;
    const int warp = t >> 5, lane = t & 31;    // warps 0..15
    const int cta = blockIdx.x;
    const int npair  = (NSLICE - cta + NCTA - 1) / NCTA;   // 3 or 4
    const int nslice = 2 * npair;
    const int nchunk = 2 * nslice;                          // 12 or 16

    const uint32_t mb0 = smem_u32(&mbar_store[0]);
    if (t == 0) {
        #pragma unroll
        for (int r = 0; r < NRING; ++r) mbar_init(mb0 + 8u * r, 1);
        s_pack[0] = 0ull;                      // armed for slice 0
    }
    __syncthreads();

    // chunk k: pair (k>>2), tensor ((k>>1)&1), half (k&1)
    auto chunk_src = [&](int k) -> const float* {
        int p = k >> 2, which = (k >> 1) & 1, half = k & 1;
        const float* base = which ? b : a;
        return base + (size_t)(cta + p * NCTA) * HW + (size_t)half * CHUNK_FLOATS;
    };

    if (t == 0) {                              // prefill all ring slots
        #pragma unroll
        for (int k = 0; k < NRING; ++k) {
            mbar_arrive_expect(mb0 + 8u * k, CHUNK_BYTES);
            bulk_g2s(smem_u32(ring + k * CHUNK_FLOATS), chunk_src(k),
                     CHUNK_BYTES, mb0 + 8u * k);
        }
    }

    float acc = 0.0f;       // meaningful in t==0 only
    float prev_d = 0.0f;

    for (int m = 0; m < nslice; ++m) {
        const int k0 = 2 * m, k1 = 2 * m + 1;
        const int slot0 = k0 % NRING, slot1 = k1 % NRING;

        // ---------- pass 1: load 32 elems to regs, exact (max, lowest-e) ----
        float4 v[8];
        mbar_wait(mb0 + 8u * slot0, (k0 / NRING) & 1);
        {
            const float4* p = (const float4*)(ring + slot0 * CHUNK_FLOATS);
            v[0] = p[t];            v[1] = p[NTH + t];
            v[2] = p[2 * NTH + t];  v[3] = p[3 * NTH + t];
        }
        mbar_wait(mb0 + 8u * slot1, (k1 / NRING) & 1);
        {
            const float4* p = (const float4*)(ring + slot1 * CHUNK_FLOATS);
            v[4] = p[t];            v[5] = p[NTH + t];
            v[6] = p[2 * NTH + t];  v[7] = p[3 * NTH + t];
        }
        // per-thread max with lowest-j (strict > keeps the first/lowest j;
        // e is ascending in j for a fixed thread)
        float mv = max4(v[0]);
        int   jw = 0;
        #pragma unroll
        for (int j = 1; j < 8; ++j) {
            const float mx = max4(v[j]);
            if (mx > mv) { mv = mx; jw = j; }
        }
        // resolve winning float4 without dynamic indexing (no local memory)
        float4 wv = v[0];
        #pragma unroll
        for (int j = 1; j < 8; ++j) if (jw == j) wv = v[j];
        // lowest component holding the max
        const int c = (wv.x == mv) ? 0 : (wv.y == mv) ? 1 : (wv.z == mv) ? 2 : 3;
        // e(j, c) = (j&3)*2048 + (j>>2)*8192 + 4*t + c
        const int ev = ((jw & 3) << 11) + ((jw >> 2) << 13) + (t << 2) + c;

        // warp reduction: 2x redux.sync (values >= 0 -> bits are monotonic)
        const unsigned mbits  = __float_as_uint(mv);
        const unsigned wmbits = __reduce_max_sync(0xffffffffu, mbits);
        const unsigned key    = (mbits == wmbits) ? (unsigned)(HW - ev) : 0u;
        const unsigned wkey   = __reduce_max_sync(0xffffffffu, key);
        if (lane == 0)
            atomicMax(&s_pack[m & 1],
                      ((unsigned long long)wmbits << 32) | (unsigned long long)wkey);
        __syncthreads();                       // BAR1: ring slots free, pack final

        // refill freed slots ASAP (warp 1; overlaps pass-2 startup)
        if (t == 32) {
            if (k0 + NRING < nchunk) {
                mbar_arrive_expect(mb0 + 8u * slot0, CHUNK_BYTES);
                bulk_g2s(smem_u32(ring + slot0 * CHUNK_FLOATS),
                         chunk_src(k0 + NRING), CHUNK_BYTES, mb0 + 8u * slot0);
            }
            if (k1 + NRING < nchunk) {
                mbar_arrive_expect(mb0 + 8u * slot1, CHUNK_BYTES);
                bulk_g2s(smem_u32(ring + slot1 * CHUNK_FLOATS),
                         chunk_src(k1 + NRING), CHUNK_BYTES, mb0 + 8u * slot1);
            }
        }

        // every thread reads the block result with one LDS.64
        const unsigned long long pk = s_pack[m & 1];
        const float bv = __uint_as_float((unsigned)(pk >> 32));
        const int   bi = HW - (int)(pk & 0xffffffffu);
        if (t == 0) s_pack[(m + 1) & 1] = 0ull;   // arm next slice's slot
                                                  // (reads of it ended before BAR1)

        // ---------- pass 2: masked distance sum from registers ---------------
        const float thr = bv * 0.5f;
        const int ym = bi >> 7;
        const int xm = bi & 127;

        // x = 4*lane + c is slice-invariant per thread
        const int xb = (lane << 2) - xm;
        const float fdx2_0 = (float)(xb * xb);
        const float fdx2_1 = (float)((xb + 1) * (xb + 1));
        const float fdx2_2 = (float)((xb + 2) * (xb + 2));
        const float fdx2_3 = (float)((xb + 3) * (xb + 3));

        float sum = 0.0f;
        int   cnt = 0;
        // y(v[j]) = 16*j + warp  (j 0..7 spans both chunks contiguously in y)
        #pragma unroll
        for (int j = 0; j < 8; ++j) {
            const int dy = (j << 4) + warp - ym;
            const float fdy2 = (float)(dy * dy);
            float d0 = fsqrt_approx(fdy2 + fdx2_0);
            float d1 = fsqrt_approx(fdy2 + fdx2_1);
            float d2 = fsqrt_approx(fdy2 + fdx2_2);
            float d3 = fsqrt_approx(fdy2 + fdx2_3);
            if (v[j].x > thr) { sum += d0; ++cnt; }
            if (v[j].y > thr) { sum += d1; ++cnt; }
            if (v[j].z > thr) { sum += d2; ++cnt; }
            if (v[j].w > thr) { sum += d3; ++cnt; }
        }
        cnt = __reduce_add_sync(0xffffffffu, cnt);   // 1 instr warp add
        #pragma unroll
        for (int off = 16; off > 0; off >>= 1)
            sum += __shfl_down_sync(0xffffffffu, sum, off);
        if (lane == 0) { s_s[warp] = sum; s_c[warp] = cnt; }
        __syncthreads();                       // BAR2: all partials written

        // warp 0 reduces in parallel; shadowed by other warps entering pass 1.
        // (its reads of s_s/s_c complete before it reaches the next BAR1/BAR2,
        // which gate the next writes to these arrays.)
        if (warp == 0) {
            float S = s_s[lane & 15];
            float C = (float)s_c[lane & 15];
            #pragma unroll
            for (int off = 8; off > 0; off >>= 1) {
                S += __shfl_xor_sync(0xffffffffu, S, off);
                C += __shfl_xor_sync(0xffffffffu, C, off);
            }
            if (lane == 0) {
                float d;
                if (bv > 0.0f) {
                    d = (C > 0.0f) ? (S / C) / MAX_DIST : 1.0f;
                } else {
                    d = 0.0f;
                }
                if (m & 1) acc += fabsf(prev_d - d);   // pair done: |d_a - d_b|
                else       prev_d = d;
            }
        }
    }

    // ---------- fused finalize: one atomic per CTA; last CTA writes + resets
    if (t == 0) {
        atomicAdd(&g_acc, acc);
        __threadfence();
        unsigned int vdone = atomicAdd(&g_done, 1u);
        if (vdone == NCTA - 1) {
            float total = atomicAdd(&g_acc, 0.0f);   // serialized read after all adds
            out[0] = total / 17.0f / 64.0f;
            g_acc = 0.0f;                            // restore invariant for next run
            __threadfence();
            g_done = 0u;
        }
    }
}

extern "C" void kernel_launch(void* const* d_in, const int* in_sizes, int n_in,
                              void* d_out, int out_size) {
    const float* a = (const float*)d_in[0];   // output heatmaps [64,17,128,128] f32
    const float* b = (const float*)d_in[1];   // target heatmaps [64,17,128,128] f32
    (void)in_sizes; (void)n_in; (void)out_size;

    const int smem_bytes = NRING * CHUNK_BYTES;   // 96 KB per CTA

    static bool attr_set = false;
    if (!attr_set) {
        cudaFuncSetAttribute(loss_kernel,
                             cudaFuncAttributeMaxDynamicSharedMemorySize, smem_bytes);
        attr_set = true;
    }

    loss_kernel<<<NCTA, NTH, smem_bytes>>>(a, b, (float*)d_out);
}